// round 15
// baseline (speedup 1.0000x reference)
#include <cuda_runtime.h>
#include <cuda_fp16.h>
#include <cstdint>
#include <math.h>

// Problem constants
#define Bc 64
#define Nn 512
#define Lk 128
#define Mm 1024

#define MT 64        // columns (m) per CTA tile (after compaction)
#define NT 64        // rows (n) per sub-chunk (double buffered)
#define NCHUNK (Nn / NT)
#define THREADS 256

// Row stride for fp16 tiles: 136 halves = 272 bytes (= 17 * 16B lanes).
#define RSTRIDE_B 272
#define ATILE_B (NT * RSTRIDE_B)        // 17408

// ---- SMEM byte layout -----------------------------------------------------
#define SB_B    0                       // Was fp16 [64 m][136 k]   17408B
#define SB_A    17408                   // A double buffer 2x17408  34816B
#define SB_SC   52224                   // s values 2 x [64] f32    512B
#define SB_COLS 52736                   // col indices [64] int     256B
#define SB_FOLD 52992                   // foldE[2][64], foldS[2][64] 1024B
#define SMEM_BYTES 55040

// prep grid split
#define CONV_BLOCKS 512                 // 8 blocks per batch, 64 rows each

// ---- device scratch (no allocations allowed) ------------------------------
__device__ int    g_list[Bc * Mm];
__device__ int    g_cnt[Bc];
__device__ __half g_Xh[Bc * Nn * Lk];   // X in fp16, [b][n][k]
__device__ __half g_WaT[Mm * Lk];       // Wa transposed fp16, [m][k]
__device__ float  g_s[Bc * Nn];

// ---- PTX helpers ----------------------------------------------------------
__device__ __forceinline__ uint32_t smem_u32(const void* p) {
    uint32_t a;
    asm("{ .reg .u64 t; cvta.to.shared.u64 t, %1; cvt.u32.u64 %0, t; }"
        : "=r"(a) : "l"(p));
    return a;
}
__device__ __forceinline__ void cp16(uint32_t dst, const void* src) {
    asm volatile("cp.async.cg.shared.global [%0], [%1], 16;"
                 :: "r"(dst), "l"(src));
}
__device__ __forceinline__ void cp_commit() {
    asm volatile("cp.async.commit_group;");
}
__device__ __forceinline__ void cp_wait0() {
    asm volatile("cp.async.wait_group 0;");
}
__device__ __forceinline__ void ldm4(uint32_t* r, uint32_t addr) {
    asm volatile("ldmatrix.sync.aligned.m8n8.x4.shared.b16 {%0,%1,%2,%3}, [%4];"
                 : "=r"(r[0]), "=r"(r[1]), "=r"(r[2]), "=r"(r[3]) : "r"(addr));
}
__device__ __forceinline__ void mma16816(float* c, const uint32_t* a,
                                         uint32_t b0, uint32_t b1) {
    asm volatile(
        "mma.sync.aligned.m16n8k16.row.col.f32.f16.f16.f32 "
        "{%0,%1,%2,%3}, {%4,%5,%6,%7}, {%8,%9}, {%0,%1,%2,%3};"
        : "+f"(c[0]), "+f"(c[1]), "+f"(c[2]), "+f"(c[3])
        : "r"(a[0]), "r"(a[1]), "r"(a[2]), "r"(a[3]), "r"(b0), "r"(b1));
}

// ---------------------------------------------------------------------------
// prep kernel (proven: 2.6us total gap). Blocks:
//   [0,64):   compaction + zero inactive outputs
//   [64,576): X f32 -> fp16 + s-vector, 64-row slices
//   [576,704): Wa transpose + fp16
// ---------------------------------------------------------------------------
__global__ void __launch_bounds__(256) prep_kernel(const float* __restrict__ X,
                                                   const int* __restrict__ K,
                                                   const float* __restrict__ Wa,
                                                   const float* __restrict__ Ws,
                                                   float* __restrict__ out) {
    const int blk = blockIdx.x;
    const int t = threadIdx.x;
    const int w = t >> 5;
    const int lane = t & 31;

    if (blk < Bc) {
        const int b = blk;
        __shared__ int wsum[8];
        int act[4];
        int cnt = 0;
#pragma unroll
        for (int i = 0; i < 4; ++i) {
            int m = t * 4 + i;
            act[i] = (K[b * Mm + m] > 0) ? 1 : 0;
            if (!act[i]) out[b * Mm + m] = 0.0f;
            cnt += act[i];
        }
        int inc = cnt;
#pragma unroll
        for (int d = 1; d < 32; d <<= 1) {
            int o = __shfl_up_sync(0xffffffffu, inc, d);
            if (lane >= d) inc += o;
        }
        if (lane == 31) wsum[w] = inc;
        __syncthreads();
        int wpre = 0;
#pragma unroll
        for (int i = 0; i < 8; ++i) wpre += (i < w) ? wsum[i] : 0;
        if (t == 255) g_cnt[b] = wpre + inc;
        int off = wpre + inc - cnt;
#pragma unroll
        for (int i = 0; i < 4; ++i)
            if (act[i]) g_list[b * Mm + off++] = t * 4 + i;
    } else if (blk < Bc + CONV_BLOCKS) {
        const int sid = blk - Bc;           // 0..511
        const int b = sid >> 3;
        const int nbase = (sid & 7) * 64;
        float4 wsv = ((const float4*)Ws)[lane];
#pragma unroll
        for (int i = 0; i < 8; ++i) {
            const int n = nbase + w + i * 8;
            const size_t roff = ((size_t)b * Nn + n) * Lk;
            float4 v = ((const float4*)(X + roff))[lane];
            __half2 h0 = __float22half2_rn(make_float2(v.x, v.y));
            __half2 h1 = __float22half2_rn(make_float2(v.z, v.w));
            uint2 pk = make_uint2(*(uint32_t*)&h0, *(uint32_t*)&h1);
            *(uint2*)&g_Xh[roff + lane * 4] = pk;
            float d = v.x * wsv.x + v.y * wsv.y + v.z * wsv.z + v.w * wsv.w;
#pragma unroll
            for (int o = 16; o > 0; o >>= 1)
                d += __shfl_xor_sync(0xffffffffu, d, o);
            if (lane == 0) g_s[b * Nn + n] = d;
        }
    } else {
        __shared__ float tile[32][33];
        int tb = blk - Bc - CONV_BLOCKS;
        int k0 = (tb & 3) * 32;
        int m0 = (tb >> 2) * 32;
        int tx = t & 31, ty = t >> 5;
#pragma unroll
        for (int j = 0; j < 32; j += 8)
            tile[ty + j][tx] = Wa[(size_t)(k0 + ty + j) * Mm + m0 + tx];
        __syncthreads();
#pragma unroll
        for (int j = 0; j < 32; j += 8)
            g_WaT[(size_t)(m0 + ty + j) * Lk + k0 + tx] =
                __float2half_rn(tile[tx][ty + j]);
    }
}

// ---------------------------------------------------------------------------
// Main fused kernel: fp16 mma.sync; B fragments loaded ONCE into registers
// (32 regs) and reused across all 8 chunks — cuts per-chunk LDSM traffic 33%.
// Warp map: wr = wid&1 owns rows wr*32..+31 (2 mt of 16),
//           wc = wid>>1 owns cols wc*16..+15 (2 n8 tiles).
// Grid (Mm/MT, Bc), 256 threads, occ 3.
// ---------------------------------------------------------------------------
__global__ void __launch_bounds__(THREADS, 3) fused_kernel(
    const float* __restrict__ bs, float* __restrict__ out) {
    extern __shared__ char smem[];
    const uint32_t sb = smem_u32(smem);
    const int t = threadIdx.x;
    const int wid = t >> 5;
    const int lane = t & 31;
    const int wr = wid & 1;
    const int wc = wid >> 1;

    const int b = blockIdx.y;
    const int A = g_cnt[b];
    const int j0 = blockIdx.x * MT;
    if (j0 >= A) return;
    const int Ac = min(MT, A - j0);

    int* cols = (int*)(smem + SB_COLS);

    if (t < MT) {
        int j = (t < Ac) ? (j0 + t) : j0;
        cols[t] = g_list[b * Mm + j];
    }
    __syncthreads();

    const __half* Xh = g_Xh + (size_t)b * Nn * Lk;
    const float* sG = g_s + b * Nn;

    // ---- prologue: cp.async B rows (64, via cols) + A chunk 0 + sC0 ----
    {
        const int row = t >> 2;                    // 0..63
        const int g4 = (t & 3) * 4;
        const __half* bsrc = g_WaT + (size_t)cols[row] * Lk;
#pragma unroll
        for (int gg = 0; gg < 4; ++gg)
            cp16(sb + SB_B + row * RSTRIDE_B + (g4 + gg) * 16,
                 bsrc + (g4 + gg) * 8);
#pragma unroll
        for (int gg = 0; gg < 4; ++gg)
            cp16(sb + SB_A + row * RSTRIDE_B + (g4 + gg) * 16,
                 Xh + (size_t)row * Lk + (g4 + gg) * 8);
        if (t < 16) cp16(sb + SB_SC + t * 16, sG + t * 4);
        cp_commit();
    }

    // ldmatrix lane address components
    const int a_row8 = (lane & 7) + ((lane >> 3) & 1) * 8;  // + wr*32 + mt*16
    const int a_cb   = (lane >> 4) * 16;                    // + kt*32
    const int b_row8 = (lane & 7) + (lane >> 4) * 8;        // + wc*16
    const int b_cb   = ((lane >> 3) & 1) * 16;              // + kt*32

    cp_wait0();
    __syncthreads();   // B + A0 + sC0 in smem

    // ---- load B fragments ONCE: 8 kt x 4 regs = 32 persistent regs ----
    uint32_t bf[8][4];
#pragma unroll
    for (int kt = 0; kt < 8; ++kt)
        ldm4(bf[kt], sb + SB_B + (wc * 16 + b_row8) * RSTRIDE_B
                     + kt * 32 + b_cb);

    // persistent softmax sums: [n8 tile][col j]
    float sumE[2][2], sumES[2][2];
#pragma unroll
    for (int nt = 0; nt < 2; ++nt) {
        sumE[nt][0] = sumE[nt][1] = 0.0f;
        sumES[nt][0] = sumES[nt][1] = 0.0f;
    }

    const int cp_n = t >> 2, cp_g = t & 3;

    for (int chunk = 0; chunk < NCHUNK; ++chunk) {
        const int buf = chunk & 1;
        if (chunk) {
            cp_wait0();
            __syncthreads();   // chunk data ready; prior GEMM (other buf) done
        }

        // ---- issue cp.async for chunk+1 into the other buffer ----
        if (chunk + 1 < NCHUNK) {
            const int n0n = (chunk + 1) * NT;
            const uint32_t abase = sb + SB_A + (buf ^ 1) * ATILE_B;
#pragma unroll
            for (int gg = 0; gg < 4; ++gg)
                cp16(abase + cp_n * RSTRIDE_B + (cp_g * 4 + gg) * 16,
                     Xh + (size_t)(n0n + cp_n) * Lk + (cp_g * 4 + gg) * 8);
            if (t < 16)
                cp16(sb + SB_SC + (buf ^ 1) * 256 + t * 16, sG + n0n + t * 4);
            cp_commit();
        }

        // ---- GEMM: 32x16x128 per warp; B from registers ----
        const uint32_t aT = sb + SB_A + buf * ATILE_B;
        float acc[2][2][4];
#pragma unroll
        for (int mt = 0; mt < 2; ++mt)
#pragma unroll
            for (int nt = 0; nt < 2; ++nt)
#pragma unroll
                for (int j = 0; j < 4; ++j) acc[mt][nt][j] = 0.0f;

#pragma unroll
        for (int kt = 0; kt < 8; ++kt) {
            uint32_t af[2][4];
#pragma unroll
            for (int mt = 0; mt < 2; ++mt)
                ldm4(af[mt], aT + (wr * 32 + mt * 16 + a_row8) * RSTRIDE_B
                             + kt * 32 + a_cb);
#pragma unroll
            for (int mt = 0; mt < 2; ++mt) {
                mma16816(acc[mt][0], af[mt], bf[kt][0], bf[kt][1]);
                mma16816(acc[mt][1], af[mt], bf[kt][2], bf[kt][3]);
            }
        }

        // ---- epilogue (registers only): exp + weighted accumulate ----
        {
            const float* sC = (const float*)(smem + SB_SC + buf * 256);
#pragma unroll
            for (int mt = 0; mt < 2; ++mt) {
                float s0 = sC[wr * 32 + mt * 16 + (lane >> 2)];
                float s1 = sC[wr * 32 + mt * 16 + 8 + (lane >> 2)];
#pragma unroll
                for (int nt = 0; nt < 2; ++nt) {
                    float e0 = __expf(acc[mt][nt][0]);
                    float e1 = __expf(acc[mt][nt][1]);
                    float e2 = __expf(acc[mt][nt][2]);
                    float e3 = __expf(acc[mt][nt][3]);
                    sumE[nt][0] += e0 + e2;
                    sumE[nt][1] += e1 + e3;
                    sumES[nt][0] += e0 * s0 + e2 * s1;
                    sumES[nt][1] += e1 * s0 + e3 * s1;
                }
            }
        }
    }

    // ---- cross-lane fold (rows within warp live on lane bits 2..4) ----
#pragma unroll
    for (int nt = 0; nt < 2; ++nt)
#pragma unroll
        for (int j = 0; j < 2; ++j) {
            float e = sumE[nt][j], s = sumES[nt][j];
            e += __shfl_xor_sync(0xffffffffu, e, 4);
            e += __shfl_xor_sync(0xffffffffu, e, 8);
            e += __shfl_xor_sync(0xffffffffu, e, 16);
            s += __shfl_xor_sync(0xffffffffu, s, 4);
            s += __shfl_xor_sync(0xffffffffu, s, 8);
            s += __shfl_xor_sync(0xffffffffu, s, 16);
            sumE[nt][j] = e;
            sumES[nt][j] = s;
        }

    float* foldE = (float*)(smem + SB_FOLD);
    float* foldS = foldE + 128;
    if (lane < 4) {
#pragma unroll
        for (int nt = 0; nt < 2; ++nt)
#pragma unroll
            for (int j = 0; j < 2; ++j) {
                int c = wc * 16 + nt * 8 + lane * 2 + j;
                foldE[wr * 64 + c] = sumE[nt][j];
                foldS[wr * 64 + c] = sumES[nt][j];
            }
    }
    __syncthreads();

    // ---- fold 2 row-groups, sigmoid, scatter ----
    if (t < Ac) {
        float se = foldE[t] + foldE[64 + t];
        float st = foldS[t] + foldS[64 + t];
        float v = st / se + bs[0];
        out[b * Mm + cols[t]] = 1.0f / (1.0f + __expf(-v));
    }
}

// ---------------------------------------------------------------------------
// Launch contract
// Inputs: X f32[4194304], K i32[65536], Wa f32[131072], ba f32[1024] (dead),
//         Ws f32[128], bs f32[1].  Output: f32[65536]
// ---------------------------------------------------------------------------
extern "C" void kernel_launch(void* const* d_in, const int* in_sizes, int n_in,
                              void* d_out, int out_size) {
    const float* X  = (const float*)d_in[0];
    const int*   K  = (const int*)d_in[1];
    const float* Wa = (const float*)d_in[2];
    const float* Ws = (const float*)d_in[4];
    const float* bs = (const float*)d_in[5];
    float* out = (float*)d_out;

    cudaFuncSetAttribute(fused_kernel, cudaFuncAttributeMaxDynamicSharedMemorySize,
                         SMEM_BYTES);

    prep_kernel<<<Bc + CONV_BLOCKS + 128, 256>>>(X, K, Wa, Ws, out);
    fused_kernel<<<dim3(Mm / MT, Bc), THREADS, SMEM_BYTES>>>(bs, out);
}

// round 17
// speedup vs baseline: 1.1378x; 1.1378x over previous
#include <cuda_runtime.h>
#include <cuda_fp16.h>
#include <cstdint>
#include <math.h>

// Problem constants
#define Bc 64
#define Nn 512
#define Lk 128
#define Mm 1024

#define MT 64        // columns (m) per CTA tile (after compaction)
#define NT 64        // rows (n) per sub-chunk (double buffered)
#define NCHUNK (Nn / NT)
#define THREADS 256

// Row stride for fp16 tiles: 136 halves = 272 bytes (= 17 * 16B lanes).
// 272 mod 128 = 16 -> consecutive rows hit distinct 16B lanes:
// conflict-free ldmatrix and conflict-free cp.async/STS phases.
#define RSTRIDE_B 272
#define ATILE_B (NT * RSTRIDE_B)        // 17408

// ---- SMEM byte layout -----------------------------------------------------
#define SB_B    0                       // Was fp16 [64 m][136 k]   17408B
#define SB_A    17408                   // A double buffer 2x17408  34816B
#define SB_SC   52224                   // s values 2 x [64] f32    512B
#define SB_COLS 52736                   // col indices [64] int     256B
#define SB_FOLD 52992                   // foldE[4][64], foldS[4][64] 2048B
#define SMEM_BYTES 55040

// prep grid split
#define CONV_BLOCKS 512                 // 8 blocks per batch, 64 rows each

// ---- device scratch (no allocations allowed) ------------------------------
__device__ int    g_list[Bc * Mm];
__device__ int    g_cnt[Bc];
__device__ __half g_Xh[Bc * Nn * Lk];   // X in fp16, [b][n][k]
__device__ __half g_WaT[Mm * Lk];       // Wa transposed fp16, [m][k]
__device__ float  g_s[Bc * Nn];

// ---- PTX helpers ----------------------------------------------------------
__device__ __forceinline__ uint32_t smem_u32(const void* p) {
    uint32_t a;
    asm("{ .reg .u64 t; cvta.to.shared.u64 t, %1; cvt.u32.u64 %0, t; }"
        : "=r"(a) : "l"(p));
    return a;
}
__device__ __forceinline__ void cp16(uint32_t dst, const void* src) {
    asm volatile("cp.async.cg.shared.global [%0], [%1], 16;"
                 :: "r"(dst), "l"(src));
}
__device__ __forceinline__ void cp_commit() {
    asm volatile("cp.async.commit_group;");
}
__device__ __forceinline__ void cp_wait0() {
    asm volatile("cp.async.wait_group 0;");
}
__device__ __forceinline__ void ldm4(uint32_t* r, uint32_t addr) {
    asm volatile("ldmatrix.sync.aligned.m8n8.x4.shared.b16 {%0,%1,%2,%3}, [%4];"
                 : "=r"(r[0]), "=r"(r[1]), "=r"(r[2]), "=r"(r[3]) : "r"(addr));
}
// NOTE: non-volatile — pure register math. Lets ptxas float HMMAs between the
// (volatile, ordered) ldmatrix stream and software-pipeline the latency.
__device__ __forceinline__ void mma16816(float* c, const uint32_t* a,
                                         uint32_t b0, uint32_t b1) {
    asm("mma.sync.aligned.m16n8k16.row.col.f32.f16.f16.f32 "
        "{%0,%1,%2,%3}, {%4,%5,%6,%7}, {%8,%9}, {%0,%1,%2,%3};"
        : "+f"(c[0]), "+f"(c[1]), "+f"(c[2]), "+f"(c[3])
        : "r"(a[0]), "r"(a[1]), "r"(a[2]), "r"(a[3]), "r"(b0), "r"(b1));
}

// ---------------------------------------------------------------------------
// prep kernel (proven: ~2.6us total gap). Blocks:
//   [0,64):   compaction + zero inactive outputs
//   [64,576): X f32 -> fp16 + s-vector, 64-row slices (full-chip)
//   [576,704): Wa transpose + fp16
// ---------------------------------------------------------------------------
__global__ void __launch_bounds__(256) prep_kernel(const float* __restrict__ X,
                                                   const int* __restrict__ K,
                                                   const float* __restrict__ Wa,
                                                   const float* __restrict__ Ws,
                                                   float* __restrict__ out) {
    const int blk = blockIdx.x;
    const int t = threadIdx.x;
    const int w = t >> 5;
    const int lane = t & 31;

    if (blk < Bc) {
        const int b = blk;
        __shared__ int wsum[8];
        int act[4];
        int cnt = 0;
#pragma unroll
        for (int i = 0; i < 4; ++i) {
            int m = t * 4 + i;
            act[i] = (K[b * Mm + m] > 0) ? 1 : 0;
            if (!act[i]) out[b * Mm + m] = 0.0f;
            cnt += act[i];
        }
        int inc = cnt;
#pragma unroll
        for (int d = 1; d < 32; d <<= 1) {
            int o = __shfl_up_sync(0xffffffffu, inc, d);
            if (lane >= d) inc += o;
        }
        if (lane == 31) wsum[w] = inc;
        __syncthreads();
        int wpre = 0;
#pragma unroll
        for (int i = 0; i < 8; ++i) wpre += (i < w) ? wsum[i] : 0;
        if (t == 255) g_cnt[b] = wpre + inc;
        int off = wpre + inc - cnt;
#pragma unroll
        for (int i = 0; i < 4; ++i)
            if (act[i]) g_list[b * Mm + off++] = t * 4 + i;
    } else if (blk < Bc + CONV_BLOCKS) {
        const int sid = blk - Bc;           // 0..511
        const int b = sid >> 3;
        const int nbase = (sid & 7) * 64;
        float4 wsv = ((const float4*)Ws)[lane];
#pragma unroll
        for (int i = 0; i < 8; ++i) {
            const int n = nbase + w + i * 8;
            const size_t roff = ((size_t)b * Nn + n) * Lk;
            float4 v = ((const float4*)(X + roff))[lane];
            __half2 h0 = __float22half2_rn(make_float2(v.x, v.y));
            __half2 h1 = __float22half2_rn(make_float2(v.z, v.w));
            uint2 pk = make_uint2(*(uint32_t*)&h0, *(uint32_t*)&h1);
            *(uint2*)&g_Xh[roff + lane * 4] = pk;
            float d = v.x * wsv.x + v.y * wsv.y + v.z * wsv.z + v.w * wsv.w;
#pragma unroll
            for (int o = 16; o > 0; o >>= 1)
                d += __shfl_xor_sync(0xffffffffu, d, o);
            if (lane == 0) g_s[b * Nn + n] = d;
        }
    } else {
        __shared__ float tile[32][33];
        int tb = blk - Bc - CONV_BLOCKS;
        int k0 = (tb & 3) * 32;
        int m0 = (tb >> 2) * 32;
        int tx = t & 31, ty = t >> 5;
#pragma unroll
        for (int j = 0; j < 32; j += 8)
            tile[ty + j][tx] = Wa[(size_t)(k0 + ty + j) * Mm + m0 + tx];
        __syncthreads();
#pragma unroll
        for (int j = 0; j < 32; j += 8)
            g_WaT[(size_t)(m0 + ty + j) * Lk + k0 + tx] =
                __float2half_rn(tile[tx][ty + j]);
    }
}

// ---------------------------------------------------------------------------
// Main fused kernel (R11 proven config: MT=64, occ 4, 16x32 warp tiles):
// fp16 mma.sync logits GEMM; B tile via coalesced cp.async row-gather from
// g_WaT; A double-buffered cp.async; max-free register softmax sums.
// Grid (Mm/MT, Bc), 256 threads.
// Warp map: wr = wid&3 owns rows wr*16..+15, wc = wid>>2 owns cols wc*32..+31.
// ---------------------------------------------------------------------------
__global__ void __launch_bounds__(THREADS, 4) fused_kernel(
    const float* __restrict__ bs, float* __restrict__ out) {
    extern __shared__ char smem[];
    const uint32_t sb = smem_u32(smem);
    const int t = threadIdx.x;
    const int wid = t >> 5;
    const int lane = t & 31;
    const int wr = wid & 3;
    const int wc = wid >> 2;

    const int b = blockIdx.y;
    const int A = g_cnt[b];
    const int j0 = blockIdx.x * MT;
    if (j0 >= A) return;
    const int Ac = min(MT, A - j0);

    int* cols = (int*)(smem + SB_COLS);

    if (t < MT) {
        int j = (t < Ac) ? (j0 + t) : j0;
        cols[t] = g_list[b * Mm + j];
    }
    __syncthreads();

    const __half* Xh = g_Xh + (size_t)b * Nn * Lk;
    const float* sG = g_s + b * Nn;

    // ---- prologue: cp.async B rows (via cols) + A chunk 0 + sC ----
    {
        const int row = t >> 2;                    // 0..63
        const int g4 = (t & 3) * 4;                // granule start (of 16)
        const __half* bsrc = g_WaT + (size_t)cols[row] * Lk;
#pragma unroll
        for (int gg = 0; gg < 4; ++gg)
            cp16(sb + SB_B + row * RSTRIDE_B + (g4 + gg) * 16,
                 bsrc + (g4 + gg) * 8);
#pragma unroll
        for (int gg = 0; gg < 4; ++gg)
            cp16(sb + SB_A + row * RSTRIDE_B + (g4 + gg) * 16,
                 Xh + (size_t)row * Lk + (g4 + gg) * 8);
        if (t < 16) cp16(sb + SB_SC + t * 16, sG + t * 4);
        cp_commit();
    }

    // ldmatrix lane address components
    const int a_row8 = (lane & 7) + ((lane >> 3) & 1) * 8;  // + wr*16
    const int a_cb   = (lane >> 4) * 16;                    // + kt*32
    const int b_row8 = (lane & 7) + (lane >> 4) * 8;        // + wc*32 + np*16
    const int b_cb   = ((lane >> 3) & 1) * 16;              // + kt*32

    // persistent softmax sums over n: [ntile 0..3][col j 0..1]
    float sumE[4][2], sumES[4][2];
#pragma unroll
    for (int nt = 0; nt < 4; ++nt) {
        sumE[nt][0] = sumE[nt][1] = 0.0f;
        sumES[nt][0] = sumES[nt][1] = 0.0f;
    }

    const int cp_n = t >> 2, cp_g = t & 3;

    for (int chunk = 0; chunk < NCHUNK; ++chunk) {
        const int buf = chunk & 1;
        cp_wait0();
        __syncthreads();   // chunk data visible; prior GEMM on other buf done

        // ---- issue cp.async for chunk+1 into the other buffer ----
        if (chunk + 1 < NCHUNK) {
            const int n0n = (chunk + 1) * NT;
            const uint32_t abase = sb + SB_A + (buf ^ 1) * ATILE_B;
#pragma unroll
            for (int gg = 0; gg < 4; ++gg)
                cp16(abase + cp_n * RSTRIDE_B + (cp_g * 4 + gg) * 16,
                     Xh + (size_t)(n0n + cp_n) * Lk + (cp_g * 4 + gg) * 8);
            if (t < 16)
                cp16(sb + SB_SC + (buf ^ 1) * 256 + t * 16, sG + n0n + t * 4);
            cp_commit();
        }

        // ---- GEMM: 16x32x128 per warp, fp16 single pass ----
        const uint32_t aT = sb + SB_A + buf * ATILE_B;
        float acc[4][4];
#pragma unroll
        for (int nt = 0; nt < 4; ++nt)
#pragma unroll
            for (int j = 0; j < 4; ++j) acc[nt][j] = 0.0f;

#pragma unroll
        for (int kt = 0; kt < 8; ++kt) {
            uint32_t af[4];
            ldm4(af, aT + (wr * 16 + a_row8) * RSTRIDE_B + kt * 32 + a_cb);
#pragma unroll
            for (int np = 0; np < 2; ++np) {
                uint32_t bf[4];
                int m = wc * 32 + np * 16 + b_row8;
                ldm4(bf, sb + SB_B + m * RSTRIDE_B + kt * 32 + b_cb);
                mma16816(acc[2 * np],     af, bf[0], bf[1]);
                mma16816(acc[2 * np + 1], af, bf[2], bf[3]);
            }
        }

        // ---- epilogue (registers only): exp + weighted accumulate ----
        {
            const float* sC = (const float*)(smem + SB_SC + buf * 256);
            float s0 = sC[wr * 16 + (lane >> 2)];
            float s1 = sC[wr * 16 + 8 + (lane >> 2)];
#pragma unroll
            for (int nt = 0; nt < 4; ++nt) {
                float e0 = __expf(acc[nt][0]);
                float e1 = __expf(acc[nt][1]);
                float e2 = __expf(acc[nt][2]);
                float e3 = __expf(acc[nt][3]);
                sumE[nt][0] += e0 + e2;
                sumE[nt][1] += e1 + e3;
                sumES[nt][0] += e0 * s0 + e2 * s1;
                sumES[nt][1] += e1 * s0 + e3 * s1;
            }
        }
    }

    // ---- cross-lane fold (rows within warp live on lane bits 2..4) ----
#pragma unroll
    for (int nt = 0; nt < 4; ++nt)
#pragma unroll
        for (int j = 0; j < 2; ++j) {
            float e = sumE[nt][j], s = sumES[nt][j];
            e += __shfl_xor_sync(0xffffffffu, e, 4);
            e += __shfl_xor_sync(0xffffffffu, e, 8);
            e += __shfl_xor_sync(0xffffffffu, e, 16);
            s += __shfl_xor_sync(0xffffffffu, s, 4);
            s += __shfl_xor_sync(0xffffffffu, s, 8);
            s += __shfl_xor_sync(0xffffffffu, s, 16);
            sumE[nt][j] = e;
            sumES[nt][j] = s;
        }

    float* foldE = (float*)(smem + SB_FOLD);
    float* foldS = foldE + 256;
    if (lane < 4) {
#pragma unroll
        for (int nt = 0; nt < 4; ++nt)
#pragma unroll
            for (int j = 0; j < 2; ++j) {
                int c = wc * 32 + nt * 8 + lane * 2 + j;
                foldE[wr * 64 + c] = sumE[nt][j];
                foldS[wr * 64 + c] = sumES[nt][j];
            }
    }
    __syncthreads();

    // ---- fold 4 row-groups, sigmoid, scatter ----
    if (t < Ac) {
        float se = foldE[t] + foldE[64 + t] + foldE[128 + t] + foldE[192 + t];
        float st = foldS[t] + foldS[64 + t] + foldS[128 + t] + foldS[192 + t];
        float v = st / se + bs[0];
        out[b * Mm + cols[t]] = 1.0f / (1.0f + __expf(-v));
    }
}

// ---------------------------------------------------------------------------
// Launch contract
// Inputs: X f32[4194304], K i32[65536], Wa f32[131072], ba f32[1024] (dead),
//         Ws f32[128], bs f32[1].  Output: f32[65536]
// ---------------------------------------------------------------------------
extern "C" void kernel_launch(void* const* d_in, const int* in_sizes, int n_in,
                              void* d_out, int out_size) {
    const float* X  = (const float*)d_in[0];
    const int*   K  = (const int*)d_in[1];
    const float* Wa = (const float*)d_in[2];
    const float* Ws = (const float*)d_in[4];
    const float* bs = (const float*)d_in[5];
    float* out = (float*)d_out;

    cudaFuncSetAttribute(fused_kernel, cudaFuncAttributeMaxDynamicSharedMemorySize,
                         SMEM_BYTES);

    prep_kernel<<<Bc + CONV_BLOCKS + 128, 256>>>(X, K, Wa, Ws, out);
    fused_kernel<<<dim3(Mm / MT, Bc), THREADS, SMEM_BYTES>>>(bs, out);
}